// round 14
// baseline (speedup 1.0000x reference)
#include <cuda_runtime.h>
#include <cuda_bf16.h>
#include <cstdint>

// ---------------------------------------------------------------------------
// SAGE 2-layer forward, GB300 (ptxas target sm_103 baseline: no tcgen05).
//   GEMMs: mma.sync m16n8k16 bf16 hi/lo split (AhBh+AhBl+AlBh), fp32 acc.
//   A operands pre-split to bf16 hi/lo in producers -> GEMM staging is pure
//   cp.async.cg 16B copies, double-buffered, single __syncthreads per chunk.
//   CSR build: hist (rank atomics) -> fused scan -> atomic-free fill.
//   Warp-per-node gathers; epilogues fused. edge_index is int32 on device.
// ---------------------------------------------------------------------------

#define N_NODES 50000
#define N_EDGES 800000
#define IN_C    128
#define HID_C   128
#define OUT_C   64
#define NB      196            // scan blocks: 196*256 = 50176 >= N_NODES
#define ROWS_PAD (NB * 256)    // 50176 padded rows (in-bounds cp.async for tail CTA)

__device__ __align__(16) __nv_bfloat16 g_xhi   [(size_t)ROWS_PAD * 128];
__device__ __align__(16) __nv_bfloat16 g_xlo   [(size_t)ROWS_PAD * 128];
__device__ __align__(16) __nv_bfloat16 g_msg1hi[(size_t)ROWS_PAD * 128];
__device__ __align__(16) __nv_bfloat16 g_msg1lo[(size_t)ROWS_PAD * 128];
__device__ __align__(16) __nv_bfloat16 g_hhi   [(size_t)ROWS_PAD * 128];
__device__ __align__(16) __nv_bfloat16 g_hlo   [(size_t)ROWS_PAD * 128];
__device__ __align__(16) float g_c2[(size_t)N_NODES * 128];   // [t=h@W2l | hr=h@W2r]

__device__ int g_deg_i[NB * 256];
__device__ int g_off  [NB * 256];
__device__ int g_rank [N_EDGES];
__device__ int g_total;
__device__ int g_csr  [950016];   // padded-deg capacity: 800000 + 3*50000

// Precomputed B fragments: uint4 {bh0, bh1, bl0, bl1} per (n_tile, ks, lane).
__device__ __align__(16) uint4 gW1frag[16 * 16 * 32];
__device__ __align__(16) uint4 gW2frag[16 * 8 * 32];

// ---------------- helpers ----------------------------------------------------
__device__ __forceinline__ uint32_t smem_u32(const void* p) {
    uint32_t a;
    asm("{ .reg .u64 t; cvta.to.shared.u64 t, %1; cvt.u32.u64 %0, t; }" : "=r"(a) : "l"(p));
    return a;
}
__device__ __forceinline__ void split2(float f0, float f1, uint32_t& hi, uint32_t& lo) {
    __nv_bfloat16 h0 = __float2bfloat16(f0);
    __nv_bfloat16 h1 = __float2bfloat16(f1);
    __nv_bfloat16 l0 = __float2bfloat16(f0 - __bfloat162float(h0));
    __nv_bfloat16 l1 = __float2bfloat16(f1 - __bfloat162float(h1));
    hi = ((uint32_t)__bfloat16_as_ushort(h1) << 16) | __bfloat16_as_ushort(h0);
    lo = ((uint32_t)__bfloat16_as_ushort(l1) << 16) | __bfloat16_as_ushort(l0);
}
__device__ __forceinline__ void ldsm4(uint32_t* r, uint32_t addr) {
    asm volatile("ldmatrix.sync.aligned.m8n8.x4.shared.b16 {%0,%1,%2,%3}, [%4];"
                 : "=r"(r[0]), "=r"(r[1]), "=r"(r[2]), "=r"(r[3]) : "r"(addr));
}
__device__ __forceinline__ void mma16816(float* d, const uint32_t* a, uint32_t b0, uint32_t b1) {
    asm volatile(
        "mma.sync.aligned.m16n8k16.row.col.f32.bf16.bf16.f32 "
        "{%0,%1,%2,%3}, {%4,%5,%6,%7}, {%8,%9}, {%0,%1,%2,%3};"
        : "+f"(d[0]), "+f"(d[1]), "+f"(d[2]), "+f"(d[3])
        : "r"(a[0]), "r"(a[1]), "r"(a[2]), "r"(a[3]), "r"(b0), "r"(b1));
}
__device__ __forceinline__ void cp16(uint32_t dst, const void* src) {
    asm volatile("cp.async.cg.shared.global [%0], [%1], 16;" :: "r"(dst), "l"(src));
}
__device__ __forceinline__ void cp_commit() {
    asm volatile("cp.async.commit_group;" ::: "memory");
}
template <int N>
__device__ __forceinline__ void cp_wait() {
    asm volatile("cp.async.wait_group %0;" :: "n"(N) : "memory");
}

// ---------------------------------------------------------------------------
// prep: zero degree array + global counter + build MMA-ready B fragments
// ---------------------------------------------------------------------------
__global__ void prep_kernel(const float* __restrict__ W1l, const float* __restrict__ W1r,
                            const float* __restrict__ W2l, const float* __restrict__ W2r) {
    int idx = blockIdx.x * blockDim.x + threadIdx.x;
    if (idx < NB * 256) g_deg_i[idx] = 0;
    if (idx == 0) g_total = 0;

    const int total1 = 16 * 16 * 32;
    const int total2 = 16 * 8 * 32;
    if (idx < total1) {
        int lane = idx & 31, ks = (idx >> 5) & 15, ntl = idx >> 9;
        int n  = ntl * 8 + (lane >> 2);
        int k0 = ks * 16 + (lane & 3) * 2;
        float f[4];
        #pragma unroll
        for (int q = 0; q < 4; ++q) {
            int k = k0 + (q >> 1) * 8 + (q & 1);
            f[q] = (k < 128) ? __ldg(W1l + (size_t)k * 128 + n)
                             : __ldg(W1r + (size_t)(k - 128) * 128 + n);
        }
        uint4 r;
        split2(f[0], f[1], r.x, r.z);
        split2(f[2], f[3], r.y, r.w);
        gW1frag[idx] = r;
    } else if (idx < total1 + total2) {
        int j = idx - total1;
        int lane = j & 31, ks = (j >> 5) & 7, ntl = j >> 8;
        int n  = ntl * 8 + (lane >> 2);
        int k0 = ks * 16 + (lane & 3) * 2;
        float f[4];
        #pragma unroll
        for (int q = 0; q < 4; ++q) {
            int k = k0 + (q >> 1) * 8 + (q & 1);
            f[q] = (n < 64) ? __ldg(W2l + (size_t)k * 64 + n)
                            : __ldg(W2r + (size_t)k * 64 + (n - 64));
        }
        uint4 r;
        split2(f[0], f[1], r.x, r.z);
        split2(f[2], f[3], r.y, r.w);
        gW2frag[j] = r;
    }
}

// ---------------------------------------------------------------------------
// xsplit: x (fp32) -> g_xhi / g_xlo (bf16 hi/lo), element-wise
// ---------------------------------------------------------------------------
__global__ void xsplit_kernel(const float* __restrict__ x) {
    int i = blockIdx.x * blockDim.x + threadIdx.x;       // float4 index
    if (i >= N_NODES * 128 / 4) return;
    float4 v = __ldg((const float4*)x + i);
    uint32_t h01, l01, h23, l23;
    split2(v.x, v.y, h01, l01);
    split2(v.z, v.w, h23, l23);
    *(uint2*)((char*)g_xhi + (size_t)i * 8) = make_uint2(h01, h23);
    *(uint2*)((char*)g_xlo + (size_t)i * 8) = make_uint2(l01, l23);
}

// ---------------------------------------------------------------------------
// CSR build: hist records each edge's rank within its dst region (2 edges/thr).
// ---------------------------------------------------------------------------
__global__ void hist_kernel(const int* __restrict__ ei) {
    int t = blockIdx.x * blockDim.x + threadIdx.x;
    int e = t * 2;
    if (e >= N_EDGES) return;
    int2 s2 = *(const int2*)(ei + e);
    int2 d2 = *(const int2*)(ei + N_EDGES + e);
    if ((unsigned)s2.x < N_NODES && (unsigned)d2.x < N_NODES)
        g_rank[e] = atomicAdd(&g_deg_i[d2.x], 1);
    if ((unsigned)s2.y < N_NODES && (unsigned)d2.y < N_NODES)
        g_rank[e + 1] = atomicAdd(&g_deg_i[d2.y], 1);
}

__device__ __forceinline__ int warp_incl_scan(int v, int lane) {
    #pragma unroll
    for (int d = 1; d < 32; d <<= 1) {
        int u = __shfl_up_sync(0xFFFFFFFFu, v, d);
        if (lane >= d) v += u;
    }
    return v;
}
__global__ void scan_fused() {
    __shared__ int wsum[8];
    __shared__ int base_s;
    int t = threadIdx.x, lane = t & 31, w = t >> 5;
    int n = blockIdx.x * 256 + t;
    int v = (n < N_NODES) ? ((g_deg_i[n] + 3) & ~3) : 0;   // pad region to 16B
    int incl = warp_incl_scan(v, lane);
    if (lane == 31) wsum[w] = incl;
    __syncthreads();
    if (w == 0) {
        int s = (lane < 8) ? wsum[lane] : 0;
        s = warp_incl_scan(s, lane);
        if (lane < 8) wsum[lane] = s;
    }
    __syncthreads();
    int wbase = (w > 0) ? wsum[w - 1] : 0;
    if (t == 255) base_s = atomicAdd(&g_total, wbase + incl);   // block sum
    __syncthreads();
    g_off[n] = base_s + wbase + incl - v;   // exclusive
}

__global__ void fill_kernel(const int* __restrict__ ei) {
    int t = blockIdx.x * blockDim.x + threadIdx.x;
    int e = t * 2;
    if (e >= N_EDGES) return;
    int2 s2 = *(const int2*)(ei + e);
    int2 d2 = *(const int2*)(ei + N_EDGES + e);
    int2 r2 = *(const int2*)(g_rank + e);
    if ((unsigned)s2.x < N_NODES && (unsigned)d2.x < N_NODES)
        g_csr[__ldg(g_off + d2.x) + r2.x] = s2.x;
    if ((unsigned)s2.y < N_NODES && (unsigned)d2.y < N_NODES)
        g_csr[__ldg(g_off + d2.y) + r2.y] = s2.y;
}

// ---------------------------------------------------------------------------
// agg1: msg1[n] = mean of x[src]; writes bf16 hi/lo split (exactly the values
// the old GEMM staging would have produced).
// ---------------------------------------------------------------------------
__global__ void __launch_bounds__(256) agg1_kernel(const float* __restrict__ x) {
    int w    = (blockIdx.x * blockDim.x + threadIdx.x) >> 5;
    int lane = threadIdx.x & 31;
    if (w >= N_NODES) return;
    int deg = g_deg_i[w];
    int off = g_off[w];
    float4 acc = make_float4(0.f, 0.f, 0.f, 0.f);
    int i = 0;
    for (; i + 4 <= deg; i += 4) {
        int4 s4 = __ldg((const int4*)(g_csr + off + i));
        float4 v0 = __ldg((const float4*)(x + (size_t)s4.x * 128) + lane);
        float4 v1 = __ldg((const float4*)(x + (size_t)s4.y * 128) + lane);
        float4 v2 = __ldg((const float4*)(x + (size_t)s4.z * 128) + lane);
        float4 v3 = __ldg((const float4*)(x + (size_t)s4.w * 128) + lane);
        acc.x += v0.x + v1.x + v2.x + v3.x;
        acc.y += v0.y + v1.y + v2.y + v3.y;
        acc.z += v0.z + v1.z + v2.z + v3.z;
        acc.w += v0.w + v1.w + v2.w + v3.w;
    }
    for (; i < deg; ++i) {
        int s = __ldg(g_csr + off + i);
        float4 v = __ldg((const float4*)(x + (size_t)s * 128) + lane);
        acc.x += v.x; acc.y += v.y; acc.z += v.z; acc.w += v.w;
    }
    float rd = 1.0f / fmaxf((float)deg, 1.0f);
    acc.x *= rd; acc.y *= rd; acc.z *= rd; acc.w *= rd;
    uint32_t h01, l01, h23, l23;
    split2(acc.x, acc.y, h01, l01);
    split2(acc.z, acc.w, h23, l23);
    size_t eoff = ((size_t)w * 128 + lane * 4) * 2;   // byte offset
    *(uint2*)((char*)g_msg1hi + eoff) = make_uint2(h01, h23);
    *(uint2*)((char*)g_msg1lo + eoff) = make_uint2(l01, l23);
}

// ---------------------------------------------------------------------------
// agg2 + final epilogue: out[n] = mean(t[src]) + b2 + hr[n]   (d=64)
// ---------------------------------------------------------------------------
__global__ void __launch_bounds__(256) agg2_kernel(float* __restrict__ out,
                                                   const float* __restrict__ b2) {
    int w    = (blockIdx.x * blockDim.x + threadIdx.x) >> 5;
    int lane = threadIdx.x & 31;
    if (w >= N_NODES) return;
    int deg = g_deg_i[w];
    int off = g_off[w];
    float2 acc = make_float2(0.f, 0.f);
    int i = 0;
    for (; i + 4 <= deg; i += 4) {
        int4 s4 = __ldg((const int4*)(g_csr + off + i));
        float2 v0 = __ldg((const float2*)(g_c2 + (size_t)s4.x * 128) + lane);
        float2 v1 = __ldg((const float2*)(g_c2 + (size_t)s4.y * 128) + lane);
        float2 v2 = __ldg((const float2*)(g_c2 + (size_t)s4.z * 128) + lane);
        float2 v3 = __ldg((const float2*)(g_c2 + (size_t)s4.w * 128) + lane);
        acc.x += v0.x + v1.x + v2.x + v3.x;
        acc.y += v0.y + v1.y + v2.y + v3.y;
    }
    for (; i < deg; ++i) {
        int s = __ldg(g_csr + off + i);
        float2 v = __ldg((const float2*)(g_c2 + (size_t)s * 128) + lane);
        acc.x += v.x; acc.y += v.y;
    }
    float rd = 1.0f / fmaxf((float)deg, 1.0f);
    float2 hr = *((const float2*)(g_c2 + (size_t)w * 128 + 64) + lane);
    float2 bb = __ldg((const float2*)b2 + lane);
    float2 o;
    o.x = acc.x * rd + bb.x + hr.x;
    o.y = acc.y * rd + bb.y + hr.y;
    *((float2*)(out + (size_t)w * 64) + lane) = o;
}

// ---------------------------------------------------------------------------
// Tensor-core GEMM: 64(M) x 128(N) CTA tile, 256 thr, 8 warps.
// A staged from pre-split bf16 hi/lo arrays via cp.async.cg (16B), double-
// buffered, one __syncthreads per chunk.
// KIND 1: A = [msg1 | x] (K=256), epilogue bias+relu -> g_hhi/g_hlo
// KIND 2: A = h (K=128),          epilogue raw       -> g_c2 (fp32)
// ---------------------------------------------------------------------------
#define A_STRIDE 72   // bf16 per smem row (144B -> ldmatrix conflict-free)

template <int KIND>
__device__ __forceinline__ void gemm_mma_body(const uint4* __restrict__ Bfrag,
                                              const float* __restrict__ bias) {
    constexpr int K_TOTAL = (KIND == 1) ? 256 : 128;
    constexpr int NKS     = K_TOTAL / 16;
    constexpr int NCHUNK  = K_TOTAL / 64;

    __shared__ __nv_bfloat16 sAhi[2][64 * A_STRIDE];
    __shared__ __nv_bfloat16 sAlo[2][64 * A_STRIDE];

    const int tid    = threadIdx.x;
    const int wid    = tid >> 5;
    const int lane   = tid & 31;
    const int warp_m = wid & 1;
    const int warp_n = wid >> 1;
    const int rowBase = blockIdx.x * 64;

    uint32_t sAhi_u[2] = { smem_u32(sAhi[0]), smem_u32(sAhi[1]) };
    uint32_t sAlo_u[2] = { smem_u32(sAlo[0]), smem_u32(sAlo[1]) };

    // issue one chunk's copies: 64 rows x 128B per array; 4 cp16 per thread.
    auto issue_chunk = [&](int buf, int c) {
        const __nv_bfloat16* srchi;
        const __nv_bfloat16* srclo;
        int kbyte;
        if (KIND == 1) {
            if (c < 2) { srchi = g_msg1hi; srclo = g_msg1lo; kbyte = c * 128; }
            else       { srchi = g_xhi;    srclo = g_xlo;    kbyte = (c - 2) * 128; }
        } else {
            srchi = g_hhi; srclo = g_hlo; kbyte = c * 128;
        }
        #pragma unroll
        for (int it = 0; it < 2; ++it) {
            int idx = tid + it * 256;      // 0..511
            int row = idx >> 3;            // 0..63
            int c16 = idx & 7;
            size_t soff = (size_t)(rowBase + row) * 256 + kbyte + c16 * 16;
            uint32_t doff = row * 144 + c16 * 16;
            cp16(sAhi_u[buf] + doff, (const char*)srchi + soff);
            cp16(sAlo_u[buf] + doff, (const char*)srclo + soff);
        }
        cp_commit();
    };

    float acc[2][4][4];
    #pragma unroll
    for (int mt = 0; mt < 2; ++mt)
        #pragma unroll
        for (int nt = 0; nt < 4; ++nt)
            #pragma unroll
            for (int q = 0; q < 4; ++q) acc[mt][nt][q] = 0.f;

    issue_chunk(0, 0);

    const uint4* bptr = Bfrag + ((size_t)warp_n * 4 * NKS) * 32 + lane;

    #pragma unroll
    for (int c = 0; c < NCHUNK; ++c) {
        int buf = c & 1;
        if (c + 1 < NCHUNK) {
            issue_chunk(1 - buf, c + 1);   // buffer's readers fenced at end of c-1
            cp_wait<1>();
        } else {
            cp_wait<0>();
        }
        __syncthreads();

        #pragma unroll
        for (int ks = 0; ks < 4; ++ks) {
            int kks = c * 4 + ks;
            uint32_t ahi[2][4], alo[2][4];
            #pragma unroll
            for (int mt = 0; mt < 2; ++mt) {
                int row = warp_m * 32 + mt * 16 + (lane & 15);
                int koff = ks * 16 + (lane >> 4) * 8;
                uint32_t byteoff = (uint32_t)(row * A_STRIDE + koff) * 2;
                ldsm4(ahi[mt], sAhi_u[buf] + byteoff);
                ldsm4(alo[mt], sAlo_u[buf] + byteoff);
            }
            #pragma unroll
            for (int nt = 0; nt < 4; ++nt) {
                uint4 b = __ldg(bptr + ((size_t)nt * NKS + kks) * 32);
                #pragma unroll
                for (int mt = 0; mt < 2; ++mt) {
                    mma16816(acc[mt][nt], ahi[mt], b.x, b.y);
                    mma16816(acc[mt][nt], ahi[mt], b.z, b.w);
                    mma16816(acc[mt][nt], alo[mt], b.x, b.y);
                }
            }
        }
        __syncthreads();
    }

    #pragma unroll
    for (int mt = 0; mt < 2; ++mt) {
        int r0 = rowBase + warp_m * 32 + mt * 16 + (lane >> 2);
        #pragma unroll
        for (int nt = 0; nt < 4; ++nt) {
            int col = warp_n * 32 + nt * 8 + (lane & 3) * 2;
            float v0 = acc[mt][nt][0], v1 = acc[mt][nt][1];
            float v2 = acc[mt][nt][2], v3 = acc[mt][nt][3];
            if (KIND == 1) {
                float b0 = __ldg(bias + col), b1 = __ldg(bias + col + 1);
                v0 = fmaxf(v0 + b0, 0.f); v1 = fmaxf(v1 + b1, 0.f);
                v2 = fmaxf(v2 + b0, 0.f); v3 = fmaxf(v3 + b1, 0.f);
                uint32_t hi, lo;
                if (r0 < N_NODES) {
                    split2(v0, v1, hi, lo);
                    size_t eo = ((size_t)r0 * 128 + col) * 2;
                    *(uint32_t*)((char*)g_hhi + eo) = hi;
                    *(uint32_t*)((char*)g_hlo + eo) = lo;
                }
                if (r0 + 8 < N_NODES) {
                    split2(v2, v3, hi, lo);
                    size_t eo = ((size_t)(r0 + 8) * 128 + col) * 2;
                    *(uint32_t*)((char*)g_hhi + eo) = hi;
                    *(uint32_t*)((char*)g_hlo + eo) = lo;
                }
            } else {
                if (r0 < N_NODES)
                    *(float2*)(g_c2 + (size_t)r0 * 128 + col) = make_float2(v0, v1);
                if (r0 + 8 < N_NODES)
                    *(float2*)(g_c2 + (size_t)(r0 + 8) * 128 + col) = make_float2(v2, v3);
            }
        }
    }
}

__global__ void __launch_bounds__(256, 2) gemm1_mma(const float* __restrict__ b1) {
    gemm_mma_body<1>(gW1frag, b1);
}
__global__ void __launch_bounds__(256, 2) gemm2_mma() {
    gemm_mma_body<2>(gW2frag, nullptr);
}

// ---------------------------------------------------------------------------
extern "C" void kernel_launch(void* const* d_in, const int* in_sizes, int n_in,
                              void* d_out, int out_size) {
    const float* x   = (const float*)d_in[0];
    const int*   ei  = (const int*)d_in[1];
    const float* W1l = (const float*)d_in[2];
    const float* b1  = (const float*)d_in[3];
    const float* W1r = (const float*)d_in[4];
    const float* W2l = (const float*)d_in[5];
    const float* b2  = (const float*)d_in[6];
    const float* W2r = (const float*)d_in[7];
    float* out = (float*)d_out;

    const int EB2 = (N_EDGES / 2 + 255) / 256;     // 1563 (2 edges/thread)
    const int gemmBlocks = (N_NODES + 63) / 64;    // 782

    prep_kernel<<<NB, 256>>>(W1l, W1r, W2l, W2r);
    xsplit_kernel<<<(N_NODES * 32 + 255) / 256, 256>>>(x);
    hist_kernel<<<EB2, 256>>>(ei);
    scan_fused<<<NB, 256>>>();
    fill_kernel<<<EB2, 256>>>(ei);

    agg1_kernel<<<(N_NODES * 32 + 255) / 256, 256>>>(x);
    gemm1_mma<<<gemmBlocks, 256>>>(b1);
    gemm2_mma<<<gemmBlocks, 256>>>();
    agg2_kernel<<<(N_NODES * 32 + 255) / 256, 256>>>(out, b2);
}

// round 15
// speedup vs baseline: 1.0993x; 1.0993x over previous
#include <cuda_runtime.h>
#include <cuda_bf16.h>
#include <cstdint>

// ---------------------------------------------------------------------------
// SAGE 2-layer forward, GB300 (ptxas target sm_103 baseline: no tcgen05).
//   GEMMs: mma.sync m16n8k16 bf16 hi/lo split (AhBh+AhBl+AlBh), fp32 acc,
//          double-buffered staging with a single __syncthreads per k-chunk.
//   CSR build: hist (rank-returning atomics) -> fused scan -> atomic-free fill,
//   4 edges/thread (int4). Warp-per-node gathers; epilogues fused.
// edge_index is int32 on device.
// ---------------------------------------------------------------------------

#define N_NODES 50000
#define N_EDGES 800000
#define IN_C    128
#define HID_C   128
#define OUT_C   64
#define NB      196            // scan blocks: 196*256 = 50176 >= N_NODES

__device__ __align__(16) float g_msg1[(size_t)N_NODES * HID_C];   // mean-agg(x)
__device__ __align__(16) float g_h   [(size_t)N_NODES * HID_C];
__device__ __align__(16) float g_c2  [(size_t)N_NODES * 128];     // [t=h@W2l | hr=h@W2r]

__device__ int g_deg_i[NB * 256];
__device__ int g_off  [NB * 256];
__device__ __align__(16) int g_rank [N_EDGES];
__device__ int g_total;
__device__ int g_csr  [950016];   // padded-deg capacity: 800000 + 3*50000

// Precomputed B fragments: uint4 {bh0, bh1, bl0, bl1} per (n_tile, ks, lane).
__device__ __align__(16) uint4 gW1frag[16 * 16 * 32];
__device__ __align__(16) uint4 gW2frag[16 * 8 * 32];

// ---------------- helpers ----------------------------------------------------
__device__ __forceinline__ uint32_t smem_u32(const void* p) {
    uint32_t a;
    asm("{ .reg .u64 t; cvta.to.shared.u64 t, %1; cvt.u32.u64 %0, t; }" : "=r"(a) : "l"(p));
    return a;
}
__device__ __forceinline__ void split2(float f0, float f1, uint32_t& hi, uint32_t& lo) {
    __nv_bfloat16 h0 = __float2bfloat16(f0);
    __nv_bfloat16 h1 = __float2bfloat16(f1);
    __nv_bfloat16 l0 = __float2bfloat16(f0 - __bfloat162float(h0));
    __nv_bfloat16 l1 = __float2bfloat16(f1 - __bfloat162float(h1));
    hi = ((uint32_t)__bfloat16_as_ushort(h1) << 16) | __bfloat16_as_ushort(h0);
    lo = ((uint32_t)__bfloat16_as_ushort(l1) << 16) | __bfloat16_as_ushort(l0);
}
__device__ __forceinline__ void ldsm4(uint32_t* r, uint32_t addr) {
    asm volatile("ldmatrix.sync.aligned.m8n8.x4.shared.b16 {%0,%1,%2,%3}, [%4];"
                 : "=r"(r[0]), "=r"(r[1]), "=r"(r[2]), "=r"(r[3]) : "r"(addr));
}
__device__ __forceinline__ void mma16816(float* d, const uint32_t* a, uint32_t b0, uint32_t b1) {
    asm volatile(
        "mma.sync.aligned.m16n8k16.row.col.f32.bf16.bf16.f32 "
        "{%0,%1,%2,%3}, {%4,%5,%6,%7}, {%8,%9}, {%0,%1,%2,%3};"
        : "+f"(d[0]), "+f"(d[1]), "+f"(d[2]), "+f"(d[3])
        : "r"(a[0]), "r"(a[1]), "r"(a[2]), "r"(a[3]), "r"(b0), "r"(b1));
}

// ---------------------------------------------------------------------------
// prep: zero degree array + global counter + build MMA-ready B fragments
// ---------------------------------------------------------------------------
__global__ void prep_kernel(const float* __restrict__ W1l, const float* __restrict__ W1r,
                            const float* __restrict__ W2l, const float* __restrict__ W2r) {
    int idx = blockIdx.x * blockDim.x + threadIdx.x;
    if (idx < NB * 256) g_deg_i[idx] = 0;
    if (idx == 0) g_total = 0;

    const int total1 = 16 * 16 * 32;
    const int total2 = 16 * 8 * 32;
    if (idx < total1) {
        int lane = idx & 31, ks = (idx >> 5) & 15, ntl = idx >> 9;
        int n  = ntl * 8 + (lane >> 2);
        int k0 = ks * 16 + (lane & 3) * 2;
        float f[4];
        #pragma unroll
        for (int q = 0; q < 4; ++q) {
            int k = k0 + (q >> 1) * 8 + (q & 1);
            f[q] = (k < 128) ? __ldg(W1l + (size_t)k * 128 + n)
                             : __ldg(W1r + (size_t)(k - 128) * 128 + n);
        }
        uint4 r;
        split2(f[0], f[1], r.x, r.z);
        split2(f[2], f[3], r.y, r.w);
        gW1frag[idx] = r;
    } else if (idx < total1 + total2) {
        int j = idx - total1;
        int lane = j & 31, ks = (j >> 5) & 7, ntl = j >> 8;
        int n  = ntl * 8 + (lane >> 2);
        int k0 = ks * 16 + (lane & 3) * 2;
        float f[4];
        #pragma unroll
        for (int q = 0; q < 4; ++q) {
            int k = k0 + (q >> 1) * 8 + (q & 1);
            f[q] = (n < 64) ? __ldg(W2l + (size_t)k * 64 + n)
                            : __ldg(W2r + (size_t)k * 64 + (n - 64));
        }
        uint4 r;
        split2(f[0], f[1], r.x, r.z);
        split2(f[2], f[3], r.y, r.w);
        gW2frag[j] = r;
    }
}

// ---------------------------------------------------------------------------
// CSR build: hist records each edge's rank within its dst region (4 edges/thr).
// ---------------------------------------------------------------------------
__global__ void hist_kernel(const int* __restrict__ ei) {
    int t = blockIdx.x * blockDim.x + threadIdx.x;
    int e = t * 4;
    if (e >= N_EDGES) return;
    int4 s4 = *(const int4*)(ei + e);
    int4 d4 = *(const int4*)(ei + N_EDGES + e);
    int4 r4;
    r4.x = ((unsigned)s4.x < N_NODES && (unsigned)d4.x < N_NODES) ? atomicAdd(&g_deg_i[d4.x], 1) : 0;
    r4.y = ((unsigned)s4.y < N_NODES && (unsigned)d4.y < N_NODES) ? atomicAdd(&g_deg_i[d4.y], 1) : 0;
    r4.z = ((unsigned)s4.z < N_NODES && (unsigned)d4.z < N_NODES) ? atomicAdd(&g_deg_i[d4.z], 1) : 0;
    r4.w = ((unsigned)s4.w < N_NODES && (unsigned)d4.w < N_NODES) ? atomicAdd(&g_deg_i[d4.w], 1) : 0;
    *(int4*)(g_rank + e) = r4;
}

__device__ __forceinline__ int warp_incl_scan(int v, int lane) {
    #pragma unroll
    for (int d = 1; d < 32; d <<= 1) {
        int u = __shfl_up_sync(0xFFFFFFFFu, v, d);
        if (lane >= d) v += u;
    }
    return v;
}
// Fused scan: block-local exclusive scan of padded degrees; block base via
// atomicAdd on g_total (CSR regions need only be disjoint, not node-ordered).
__global__ void scan_fused() {
    __shared__ int wsum[8];
    __shared__ int base_s;
    int t = threadIdx.x, lane = t & 31, w = t >> 5;
    int n = blockIdx.x * 256 + t;
    int v = (n < N_NODES) ? ((g_deg_i[n] + 3) & ~3) : 0;   // pad region to 16B
    int incl = warp_incl_scan(v, lane);
    if (lane == 31) wsum[w] = incl;
    __syncthreads();
    if (w == 0) {
        int s = (lane < 8) ? wsum[lane] : 0;
        s = warp_incl_scan(s, lane);
        if (lane < 8) wsum[lane] = s;
    }
    __syncthreads();
    int wbase = (w > 0) ? wsum[w - 1] : 0;
    if (t == 255) base_s = atomicAdd(&g_total, wbase + incl);   // block sum
    __syncthreads();
    g_off[n] = base_s + wbase + incl - v;   // exclusive
}

// Atomic-free fill: slot = off[dst] + rank[e]. off table is L1/L2-resident.
__global__ void fill_kernel(const int* __restrict__ ei) {
    int t = blockIdx.x * blockDim.x + threadIdx.x;
    int e = t * 4;
    if (e >= N_EDGES) return;
    int4 s4 = *(const int4*)(ei + e);
    int4 d4 = *(const int4*)(ei + N_EDGES + e);
    int4 r4 = *(const int4*)(g_rank + e);
    if ((unsigned)s4.x < N_NODES && (unsigned)d4.x < N_NODES)
        g_csr[__ldg(g_off + d4.x) + r4.x] = s4.x;
    if ((unsigned)s4.y < N_NODES && (unsigned)d4.y < N_NODES)
        g_csr[__ldg(g_off + d4.y) + r4.y] = s4.y;
    if ((unsigned)s4.z < N_NODES && (unsigned)d4.z < N_NODES)
        g_csr[__ldg(g_off + d4.z) + r4.z] = s4.z;
    if ((unsigned)s4.w < N_NODES && (unsigned)d4.w < N_NODES)
        g_csr[__ldg(g_off + d4.w) + r4.w] = s4.w;
}

// ---------------------------------------------------------------------------
// agg1: msg1[n] = mean of x[src] over incoming edges (warp per node, d=128)
// ---------------------------------------------------------------------------
__global__ void __launch_bounds__(256) agg1_kernel(const float* __restrict__ x) {
    int w    = (blockIdx.x * blockDim.x + threadIdx.x) >> 5;
    int lane = threadIdx.x & 31;
    if (w >= N_NODES) return;
    int deg = g_deg_i[w];
    int off = g_off[w];
    float4 acc = make_float4(0.f, 0.f, 0.f, 0.f);
    int i = 0;
    for (; i + 4 <= deg; i += 4) {
        int4 s4 = __ldg((const int4*)(g_csr + off + i));
        float4 v0 = __ldg((const float4*)(x + (size_t)s4.x * 128) + lane);
        float4 v1 = __ldg((const float4*)(x + (size_t)s4.y * 128) + lane);
        float4 v2 = __ldg((const float4*)(x + (size_t)s4.z * 128) + lane);
        float4 v3 = __ldg((const float4*)(x + (size_t)s4.w * 128) + lane);
        acc.x += v0.x + v1.x + v2.x + v3.x;
        acc.y += v0.y + v1.y + v2.y + v3.y;
        acc.z += v0.z + v1.z + v2.z + v3.z;
        acc.w += v0.w + v1.w + v2.w + v3.w;
    }
    for (; i < deg; ++i) {
        int s = __ldg(g_csr + off + i);
        float4 v = __ldg((const float4*)(x + (size_t)s * 128) + lane);
        acc.x += v.x; acc.y += v.y; acc.z += v.z; acc.w += v.w;
    }
    float rd = 1.0f / fmaxf((float)deg, 1.0f);
    acc.x *= rd; acc.y *= rd; acc.z *= rd; acc.w *= rd;
    *((float4*)(g_msg1 + (size_t)w * 128) + lane) = acc;
}

// ---------------------------------------------------------------------------
// agg2 + final epilogue: out[n] = mean(t[src]) + b2 + hr[n]   (d=64)
// ---------------------------------------------------------------------------
__global__ void __launch_bounds__(256) agg2_kernel(float* __restrict__ out,
                                                   const float* __restrict__ b2) {
    int w    = (blockIdx.x * blockDim.x + threadIdx.x) >> 5;
    int lane = threadIdx.x & 31;
    if (w >= N_NODES) return;
    int deg = g_deg_i[w];
    int off = g_off[w];
    float2 acc = make_float2(0.f, 0.f);
    int i = 0;
    for (; i + 4 <= deg; i += 4) {
        int4 s4 = __ldg((const int4*)(g_csr + off + i));
        float2 v0 = __ldg((const float2*)(g_c2 + (size_t)s4.x * 128) + lane);
        float2 v1 = __ldg((const float2*)(g_c2 + (size_t)s4.y * 128) + lane);
        float2 v2 = __ldg((const float2*)(g_c2 + (size_t)s4.z * 128) + lane);
        float2 v3 = __ldg((const float2*)(g_c2 + (size_t)s4.w * 128) + lane);
        acc.x += v0.x + v1.x + v2.x + v3.x;
        acc.y += v0.y + v1.y + v2.y + v3.y;
    }
    for (; i < deg; ++i) {
        int s = __ldg(g_csr + off + i);
        float2 v = __ldg((const float2*)(g_c2 + (size_t)s * 128) + lane);
        acc.x += v.x; acc.y += v.y;
    }
    float rd = 1.0f / fmaxf((float)deg, 1.0f);
    float2 hr = *((const float2*)(g_c2 + (size_t)w * 128 + 64) + lane);
    float2 bb = __ldg((const float2*)b2 + lane);
    float2 o;
    o.x = acc.x * rd + bb.x + hr.x;
    o.y = acc.y * rd + bb.y + hr.y;
    *((float2*)(out + (size_t)w * 64) + lane) = o;
}

// ---------------------------------------------------------------------------
// Tensor-core GEMM: 64(M) x 128(N) CTA tile, 256 thr, 8 warps, double-buffered.
// Single __syncthreads per k-chunk (store targets the buffer whose readers
// were already fenced by the previous barrier).
// KIND 1: A = [msg1 | x] (K=256), epilogue bias+relu -> g_h
// KIND 2: A = g_h (K=128),       epilogue raw       -> g_c2
// ---------------------------------------------------------------------------
#define A_STRIDE 72   // bf16 per smem row (144B -> ldmatrix conflict-free)

template <int KIND>
__device__ __forceinline__ void gemm_mma_body(const float* __restrict__ xin,
                                              const uint4* __restrict__ Bfrag,
                                              const float* __restrict__ bias) {
    constexpr int K_TOTAL = (KIND == 1) ? 256 : 128;
    constexpr int NKS     = K_TOTAL / 16;
    constexpr int NCHUNK  = K_TOTAL / 64;

    __shared__ __nv_bfloat16 sAhi[2][64 * A_STRIDE];
    __shared__ __nv_bfloat16 sAlo[2][64 * A_STRIDE];

    const int tid    = threadIdx.x;
    const int wid    = tid >> 5;
    const int lane   = tid & 31;
    const int warp_m = wid & 1;
    const int warp_n = wid >> 1;
    const int rowBase = blockIdx.x * 64;

    float4 pf[4];
    auto load_chunk = [&](int kb) {
        #pragma unroll
        for (int it = 0; it < 4; ++it) {
            int fid = tid + it * 256;
            int row = fid >> 4;
            int c4  = fid & 15;
            int gr  = rowBase + row;
            float4 v = make_float4(0.f, 0.f, 0.f, 0.f);
            if (gr < N_NODES) {
                if (KIND == 1) {
                    if (kb < 128)
                        v = *(const float4*)(g_msg1 + (size_t)gr * 128 + kb + c4 * 4);
                    else
                        v = __ldg((const float4*)(xin + (size_t)gr * 128 + (kb - 128) + c4 * 4));
                } else {
                    v = *(const float4*)(g_h + (size_t)gr * 128 + kb + c4 * 4);
                }
            }
            pf[it] = v;
        }
    };
    auto store_chunk = [&](int buf) {
        #pragma unroll
        for (int it = 0; it < 4; ++it) {
            int fid = tid + it * 256;
            int row = fid >> 4;
            int c4  = fid & 15;
            float4 v = pf[it];
            uint32_t h01, l01, h23, l23;
            split2(v.x, v.y, h01, l01);
            split2(v.z, v.w, h23, l23);
            int eoff = row * A_STRIDE + c4 * 4;
            *(uint32_t*)((char*)sAhi[buf] + eoff * 2)     = h01;
            *(uint32_t*)((char*)sAhi[buf] + eoff * 2 + 4) = h23;
            *(uint32_t*)((char*)sAlo[buf] + eoff * 2)     = l01;
            *(uint32_t*)((char*)sAlo[buf] + eoff * 2 + 4) = l23;
        }
    };

    float acc[2][4][4];
    #pragma unroll
    for (int mt = 0; mt < 2; ++mt)
        #pragma unroll
        for (int nt = 0; nt < 4; ++nt)
            #pragma unroll
            for (int q = 0; q < 4; ++q) acc[mt][nt][q] = 0.f;

    load_chunk(0);
    store_chunk(0);
    __syncthreads();

    const uint4* bptr = Bfrag + ((size_t)warp_n * 4 * NKS) * 32 + lane;

    #pragma unroll
    for (int c = 0; c < NCHUNK; ++c) {
        int buf = c & 1;
        if (c + 1 < NCHUNK) load_chunk((c + 1) * 64);

        const uint32_t sAhi_u = smem_u32(sAhi[buf]);
        const uint32_t sAlo_u = smem_u32(sAlo[buf]);

        #pragma unroll
        for (int ks = 0; ks < 4; ++ks) {
            int kks = c * 4 + ks;
            uint32_t ahi[2][4], alo[2][4];
            #pragma unroll
            for (int mt = 0; mt < 2; ++mt) {
                int row = warp_m * 32 + mt * 16 + (lane & 15);
                int koff = ks * 16 + (lane >> 4) * 8;
                uint32_t byteoff = (uint32_t)(row * A_STRIDE + koff) * 2;
                ldsm4(ahi[mt], sAhi_u + byteoff);
                ldsm4(alo[mt], sAlo_u + byteoff);
            }
            #pragma unroll
            for (int nt = 0; nt < 4; ++nt) {
                uint4 b = __ldg(bptr + ((size_t)nt * NKS + kks) * 32);
                #pragma unroll
                for (int mt = 0; mt < 2; ++mt) {
                    mma16816(acc[mt][nt], ahi[mt], b.x, b.y);
                    mma16816(acc[mt][nt], ahi[mt], b.z, b.w);
                    mma16816(acc[mt][nt], alo[mt], b.x, b.y);
                }
            }
        }

        if (c + 1 < NCHUNK) {
            store_chunk(1 - buf);      // buffer's last readers fenced at end of c-1
            __syncthreads();           // single barrier per chunk
        }
    }

    #pragma unroll
    for (int mt = 0; mt < 2; ++mt) {
        int r0 = rowBase + warp_m * 32 + mt * 16 + (lane >> 2);
        #pragma unroll
        for (int nt = 0; nt < 4; ++nt) {
            int col = warp_n * 32 + nt * 8 + (lane & 3) * 2;
            float v0 = acc[mt][nt][0], v1 = acc[mt][nt][1];
            float v2 = acc[mt][nt][2], v3 = acc[mt][nt][3];
            if (KIND == 1) {
                float b0 = __ldg(bias + col), b1 = __ldg(bias + col + 1);
                v0 = fmaxf(v0 + b0, 0.f); v1 = fmaxf(v1 + b1, 0.f);
                v2 = fmaxf(v2 + b0, 0.f); v3 = fmaxf(v3 + b1, 0.f);
            }
            float* dst = (KIND == 1) ? g_h : g_c2;
            if (r0 < N_NODES)
                *(float2*)(dst + (size_t)r0 * 128 + col) = make_float2(v0, v1);
            if (r0 + 8 < N_NODES)
                *(float2*)(dst + (size_t)(r0 + 8) * 128 + col) = make_float2(v2, v3);
        }
    }
}

__global__ void __launch_bounds__(256, 2) gemm1_mma(const float* __restrict__ x,
                                                    const float* __restrict__ b1) {
    gemm_mma_body<1>(x, gW1frag, b1);
}
__global__ void __launch_bounds__(256, 2) gemm2_mma() {
    gemm_mma_body<2>(nullptr, gW2frag, nullptr);
}

// ---------------------------------------------------------------------------
extern "C" void kernel_launch(void* const* d_in, const int* in_sizes, int n_in,
                              void* d_out, int out_size) {
    const float* x   = (const float*)d_in[0];
    const int*   ei  = (const int*)d_in[1];
    const float* W1l = (const float*)d_in[2];
    const float* b1  = (const float*)d_in[3];
    const float* W1r = (const float*)d_in[4];
    const float* W2l = (const float*)d_in[5];
    const float* b2  = (const float*)d_in[6];
    const float* W2r = (const float*)d_in[7];
    float* out = (float*)d_out;

    const int EB4 = (N_EDGES / 4 + 255) / 256;     // 782 (4 edges/thread)
    const int gemmBlocks = (N_NODES + 63) / 64;    // 782

    prep_kernel<<<NB, 256>>>(W1l, W1r, W2l, W2r);
    hist_kernel<<<EB4, 256>>>(ei);
    scan_fused<<<NB, 256>>>();
    fill_kernel<<<EB4, 256>>>(ei);

    agg1_kernel<<<(N_NODES * 32 + 255) / 256, 256>>>(x);
    gemm1_mma<<<gemmBlocks, 256>>>(x, b1);
    gemm2_mma<<<gemmBlocks, 256>>>();
    agg2_kernel<<<(N_NODES * 32 + 255) / 256, 256>>>(out, b2);
}

// round 16
// speedup vs baseline: 1.1349x; 1.0324x over previous
#include <cuda_runtime.h>
#include <cuda_bf16.h>
#include <cstdint>

// ---------------------------------------------------------------------------
// SAGE 2-layer forward, GB300 (ptxas target sm_103 baseline: no tcgen05).
//   GEMMs: mma.sync m16n8k16 bf16 hi/lo split (AhBh+AhBl+AlBh), fp32 acc,
//          double-buffered staging, single __syncthreads per k-chunk.
//   CSR build: hist (rank atomics, 4 edges/thr) -> fused scan -> atomic-free fill.
//   Launch chain uses PDL (programmatic dependent launch): dependent kernels
//   start early and block on cudaGridDependencySynchronize() before touching
//   predecessor data -> launch ramps overlap predecessor drain.
// edge_index is int32 on device.
// ---------------------------------------------------------------------------

#define N_NODES 50000
#define N_EDGES 800000
#define IN_C    128
#define HID_C   128
#define OUT_C   64
#define NB      196            // scan blocks: 196*256 = 50176 >= N_NODES

__device__ __align__(16) float g_msg1[(size_t)N_NODES * HID_C];   // mean-agg(x)
__device__ __align__(16) float g_h   [(size_t)N_NODES * HID_C];
__device__ __align__(16) float g_c2  [(size_t)N_NODES * 128];     // [t=h@W2l | hr=h@W2r]

__device__ int g_deg_i[NB * 256];
__device__ int g_off  [NB * 256];
__device__ __align__(16) int g_rank [N_EDGES];
__device__ int g_total;
__device__ int g_csr  [950016];   // padded-deg capacity: 800000 + 3*50000

// Precomputed B fragments: uint4 {bh0, bh1, bl0, bl1} per (n_tile, ks, lane).
__device__ __align__(16) uint4 gW1frag[16 * 16 * 32];
__device__ __align__(16) uint4 gW2frag[16 * 8 * 32];

// ---------------- helpers ----------------------------------------------------
__device__ __forceinline__ uint32_t smem_u32(const void* p) {
    uint32_t a;
    asm("{ .reg .u64 t; cvta.to.shared.u64 t, %1; cvt.u32.u64 %0, t; }" : "=r"(a) : "l"(p));
    return a;
}
__device__ __forceinline__ void split2(float f0, float f1, uint32_t& hi, uint32_t& lo) {
    __nv_bfloat16 h0 = __float2bfloat16(f0);
    __nv_bfloat16 h1 = __float2bfloat16(f1);
    __nv_bfloat16 l0 = __float2bfloat16(f0 - __bfloat162float(h0));
    __nv_bfloat16 l1 = __float2bfloat16(f1 - __bfloat162float(h1));
    hi = ((uint32_t)__bfloat16_as_ushort(h1) << 16) | __bfloat16_as_ushort(h0);
    lo = ((uint32_t)__bfloat16_as_ushort(l1) << 16) | __bfloat16_as_ushort(l0);
}
__device__ __forceinline__ void ldsm4(uint32_t* r, uint32_t addr) {
    asm volatile("ldmatrix.sync.aligned.m8n8.x4.shared.b16 {%0,%1,%2,%3}, [%4];"
                 : "=r"(r[0]), "=r"(r[1]), "=r"(r[2]), "=r"(r[3]) : "r"(addr));
}
__device__ __forceinline__ void mma16816(float* d, const uint32_t* a, uint32_t b0, uint32_t b1) {
    asm volatile(
        "mma.sync.aligned.m16n8k16.row.col.f32.bf16.bf16.f32 "
        "{%0,%1,%2,%3}, {%4,%5,%6,%7}, {%8,%9}, {%0,%1,%2,%3};"
        : "+f"(d[0]), "+f"(d[1]), "+f"(d[2]), "+f"(d[3])
        : "r"(a[0]), "r"(a[1]), "r"(a[2]), "r"(a[3]), "r"(b0), "r"(b1));
}
__device__ __forceinline__ void grid_dep_sync() {
    asm volatile("griddepcontrol.wait;" ::: "memory");
}

// ---------------------------------------------------------------------------
// prep: zero degree array + global counter + build MMA-ready B fragments
// ---------------------------------------------------------------------------
__global__ void prep_kernel(const float* __restrict__ W1l, const float* __restrict__ W1r,
                            const float* __restrict__ W2l, const float* __restrict__ W2r) {
    int idx = blockIdx.x * blockDim.x + threadIdx.x;
    if (idx < NB * 256) g_deg_i[idx] = 0;
    if (idx == 0) g_total = 0;

    const int total1 = 16 * 16 * 32;
    const int total2 = 16 * 8 * 32;
    if (idx < total1) {
        int lane = idx & 31, ks = (idx >> 5) & 15, ntl = idx >> 9;
        int n  = ntl * 8 + (lane >> 2);
        int k0 = ks * 16 + (lane & 3) * 2;
        float f[4];
        #pragma unroll
        for (int q = 0; q < 4; ++q) {
            int k = k0 + (q >> 1) * 8 + (q & 1);
            f[q] = (k < 128) ? __ldg(W1l + (size_t)k * 128 + n)
                             : __ldg(W1r + (size_t)(k - 128) * 128 + n);
        }
        uint4 r;
        split2(f[0], f[1], r.x, r.z);
        split2(f[2], f[3], r.y, r.w);
        gW1frag[idx] = r;
    } else if (idx < total1 + total2) {
        int j = idx - total1;
        int lane = j & 31, ks = (j >> 5) & 7, ntl = j >> 8;
        int n  = ntl * 8 + (lane >> 2);
        int k0 = ks * 16 + (lane & 3) * 2;
        float f[4];
        #pragma unroll
        for (int q = 0; q < 4; ++q) {
            int k = k0 + (q >> 1) * 8 + (q & 1);
            f[q] = (n < 64) ? __ldg(W2l + (size_t)k * 64 + n)
                            : __ldg(W2r + (size_t)k * 64 + (n - 64));
        }
        uint4 r;
        split2(f[0], f[1], r.x, r.z);
        split2(f[2], f[3], r.y, r.w);
        gW2frag[j] = r;
    }
}

// ---------------------------------------------------------------------------
// CSR build: hist records each edge's rank within its dst region (4 edges/thr).
// ei loads are independent of the predecessor -> issue before grid_dep_sync.
// ---------------------------------------------------------------------------
__global__ void hist_kernel(const int* __restrict__ ei) {
    int t = blockIdx.x * blockDim.x + threadIdx.x;
    int e = t * 4;
    if (e >= N_EDGES) return;
    int4 s4 = *(const int4*)(ei + e);
    int4 d4 = *(const int4*)(ei + N_EDGES + e);
    grid_dep_sync();   // g_deg_i must be zeroed (prep)
    int4 r4;
    r4.x = ((unsigned)s4.x < N_NODES && (unsigned)d4.x < N_NODES) ? atomicAdd(&g_deg_i[d4.x], 1) : 0;
    r4.y = ((unsigned)s4.y < N_NODES && (unsigned)d4.y < N_NODES) ? atomicAdd(&g_deg_i[d4.y], 1) : 0;
    r4.z = ((unsigned)s4.z < N_NODES && (unsigned)d4.z < N_NODES) ? atomicAdd(&g_deg_i[d4.z], 1) : 0;
    r4.w = ((unsigned)s4.w < N_NODES && (unsigned)d4.w < N_NODES) ? atomicAdd(&g_deg_i[d4.w], 1) : 0;
    *(int4*)(g_rank + e) = r4;
}

__device__ __forceinline__ int warp_incl_scan(int v, int lane) {
    #pragma unroll
    for (int d = 1; d < 32; d <<= 1) {
        int u = __shfl_up_sync(0xFFFFFFFFu, v, d);
        if (lane >= d) v += u;
    }
    return v;
}
// Fused scan: block-local exclusive scan of padded degrees; block base via
// atomicAdd on g_total.
__global__ void scan_fused() {
    __shared__ int wsum[8];
    __shared__ int base_s;
    int t = threadIdx.x, lane = t & 31, w = t >> 5;
    int n = blockIdx.x * 256 + t;
    grid_dep_sync();   // g_deg_i final (hist)
    int v = (n < N_NODES) ? ((g_deg_i[n] + 3) & ~3) : 0;   // pad region to 16B
    int incl = warp_incl_scan(v, lane);
    if (lane == 31) wsum[w] = incl;
    __syncthreads();
    if (w == 0) {
        int s = (lane < 8) ? wsum[lane] : 0;
        s = warp_incl_scan(s, lane);
        if (lane < 8) wsum[lane] = s;
    }
    __syncthreads();
    int wbase = (w > 0) ? wsum[w - 1] : 0;
    if (t == 255) base_s = atomicAdd(&g_total, wbase + incl);   // block sum
    __syncthreads();
    g_off[n] = base_s + wbase + incl - v;   // exclusive
}

// Atomic-free fill: slot = off[dst] + rank[e].
__global__ void fill_kernel(const int* __restrict__ ei) {
    int t = blockIdx.x * blockDim.x + threadIdx.x;
    int e = t * 4;
    if (e >= N_EDGES) return;
    int4 s4 = *(const int4*)(ei + e);
    int4 d4 = *(const int4*)(ei + N_EDGES + e);
    grid_dep_sync();   // g_off (scan) ; g_rank written by hist (2 back, transitive)
    int4 r4 = *(const int4*)(g_rank + e);
    if ((unsigned)s4.x < N_NODES && (unsigned)d4.x < N_NODES)
        g_csr[__ldg(g_off + d4.x) + r4.x] = s4.x;
    if ((unsigned)s4.y < N_NODES && (unsigned)d4.y < N_NODES)
        g_csr[__ldg(g_off + d4.y) + r4.y] = s4.y;
    if ((unsigned)s4.z < N_NODES && (unsigned)d4.z < N_NODES)
        g_csr[__ldg(g_off + d4.z) + r4.z] = s4.z;
    if ((unsigned)s4.w < N_NODES && (unsigned)d4.w < N_NODES)
        g_csr[__ldg(g_off + d4.w) + r4.w] = s4.w;
}

// ---------------------------------------------------------------------------
// agg1: msg1[n] = mean of x[src] over incoming edges (warp per node, d=128)
// ---------------------------------------------------------------------------
__global__ void __launch_bounds__(256) agg1_kernel(const float* __restrict__ x) {
    int w    = (blockIdx.x * blockDim.x + threadIdx.x) >> 5;
    int lane = threadIdx.x & 31;
    grid_dep_sync();   // g_csr / g_off / g_deg_i final
    if (w >= N_NODES) return;
    int deg = g_deg_i[w];
    int off = g_off[w];
    float4 acc = make_float4(0.f, 0.f, 0.f, 0.f);
    int i = 0;
    for (; i + 4 <= deg; i += 4) {
        int4 s4 = __ldg((const int4*)(g_csr + off + i));
        float4 v0 = __ldg((const float4*)(x + (size_t)s4.x * 128) + lane);
        float4 v1 = __ldg((const float4*)(x + (size_t)s4.y * 128) + lane);
        float4 v2 = __ldg((const float4*)(x + (size_t)s4.z * 128) + lane);
        float4 v3 = __ldg((const float4*)(x + (size_t)s4.w * 128) + lane);
        acc.x += v0.x + v1.x + v2.x + v3.x;
        acc.y += v0.y + v1.y + v2.y + v3.y;
        acc.z += v0.z + v1.z + v2.z + v3.z;
        acc.w += v0.w + v1.w + v2.w + v3.w;
    }
    for (; i < deg; ++i) {
        int s = __ldg(g_csr + off + i);
        float4 v = __ldg((const float4*)(x + (size_t)s * 128) + lane);
        acc.x += v.x; acc.y += v.y; acc.z += v.z; acc.w += v.w;
    }
    float rd = 1.0f / fmaxf((float)deg, 1.0f);
    acc.x *= rd; acc.y *= rd; acc.z *= rd; acc.w *= rd;
    *((float4*)(g_msg1 + (size_t)w * 128) + lane) = acc;
}

// ---------------------------------------------------------------------------
// agg2 + final epilogue: out[n] = mean(t[src]) + b2 + hr[n]   (d=64)
// ---------------------------------------------------------------------------
__global__ void __launch_bounds__(256) agg2_kernel(float* __restrict__ out,
                                                   const float* __restrict__ b2) {
    int w    = (blockIdx.x * blockDim.x + threadIdx.x) >> 5;
    int lane = threadIdx.x & 31;
    grid_dep_sync();   // g_c2 final (gemm2)
    if (w >= N_NODES) return;
    int deg = g_deg_i[w];
    int off = g_off[w];
    float2 acc = make_float2(0.f, 0.f);
    int i = 0;
    for (; i + 4 <= deg; i += 4) {
        int4 s4 = __ldg((const int4*)(g_csr + off + i));
        float2 v0 = __ldg((const float2*)(g_c2 + (size_t)s4.x * 128) + lane);
        float2 v1 = __ldg((const float2*)(g_c2 + (size_t)s4.y * 128) + lane);
        float2 v2 = __ldg((const float2*)(g_c2 + (size_t)s4.z * 128) + lane);
        float2 v3 = __ldg((const float2*)(g_c2 + (size_t)s4.w * 128) + lane);
        acc.x += v0.x + v1.x + v2.x + v3.x;
        acc.y += v0.y + v1.y + v2.y + v3.y;
    }
    for (; i < deg; ++i) {
        int s = __ldg(g_csr + off + i);
        float2 v = __ldg((const float2*)(g_c2 + (size_t)s * 128) + lane);
        acc.x += v.x; acc.y += v.y;
    }
    float rd = 1.0f / fmaxf((float)deg, 1.0f);
    float2 hr = *((const float2*)(g_c2 + (size_t)w * 128 + 64) + lane);
    float2 bb = __ldg((const float2*)b2 + lane);
    float2 o;
    o.x = acc.x * rd + bb.x + hr.x;
    o.y = acc.y * rd + bb.y + hr.y;
    *((float2*)(out + (size_t)w * 64) + lane) = o;
}

// ---------------------------------------------------------------------------
// Tensor-core GEMM: 64(M) x 128(N) CTA tile, 256 thr, 8 warps, double-buffered.
// Single __syncthreads per k-chunk.
// KIND 1: A = [msg1 | x] (K=256), epilogue bias+relu -> g_h
// KIND 2: A = g_h (K=128),       epilogue raw       -> g_c2
// ---------------------------------------------------------------------------
#define A_STRIDE 72   // bf16 per smem row (144B -> ldmatrix conflict-free)

template <int KIND>
__device__ __forceinline__ void gemm_mma_body(const float* __restrict__ xin,
                                              const uint4* __restrict__ Bfrag,
                                              const float* __restrict__ bias) {
    constexpr int K_TOTAL = (KIND == 1) ? 256 : 128;
    constexpr int NKS     = K_TOTAL / 16;
    constexpr int NCHUNK  = K_TOTAL / 64;

    __shared__ __nv_bfloat16 sAhi[2][64 * A_STRIDE];
    __shared__ __nv_bfloat16 sAlo[2][64 * A_STRIDE];

    const int tid    = threadIdx.x;
    const int wid    = tid >> 5;
    const int lane   = tid & 31;
    const int warp_m = wid & 1;
    const int warp_n = wid >> 1;
    const int rowBase = blockIdx.x * 64;

    grid_dep_sync();   // predecessor outputs (msg1 / g_h) final

    float4 pf[4];
    auto load_chunk = [&](int kb) {
        #pragma unroll
        for (int it = 0; it < 4; ++it) {
            int fid = tid + it * 256;
            int row = fid >> 4;
            int c4  = fid & 15;
            int gr  = rowBase + row;
            float4 v = make_float4(0.f, 0.f, 0.f, 0.f);
            if (gr < N_NODES) {
                if (KIND == 1) {
                    if (kb < 128)
                        v = *(const float4*)(g_msg1 + (size_t)gr * 128 + kb + c4 * 4);
                    else
                        v = __ldg((const float4*)(xin + (size_t)gr * 128 + (kb - 128) + c4 * 4));
                } else {
                    v = *(const float4*)(g_h + (size_t)gr * 128 + kb + c4 * 4);
                }
            }
            pf[it] = v;
        }
    };
    auto store_chunk = [&](int buf) {
        #pragma unroll
        for (int it = 0; it < 4; ++it) {
            int fid = tid + it * 256;
            int row = fid >> 4;
            int c4  = fid & 15;
            float4 v = pf[it];
            uint32_t h01, l01, h23, l23;
            split2(v.x, v.y, h01, l01);
            split2(v.z, v.w, h23, l23);
            int eoff = row * A_STRIDE + c4 * 4;
            *(uint32_t*)((char*)sAhi[buf] + eoff * 2)     = h01;
            *(uint32_t*)((char*)sAhi[buf] + eoff * 2 + 4) = h23;
            *(uint32_t*)((char*)sAlo[buf] + eoff * 2)     = l01;
            *(uint32_t*)((char*)sAlo[buf] + eoff * 2 + 4) = l23;
        }
    };

    float acc[2][4][4];
    #pragma unroll
    for (int mt = 0; mt < 2; ++mt)
        #pragma unroll
        for (int nt = 0; nt < 4; ++nt)
            #pragma unroll
            for (int q = 0; q < 4; ++q) acc[mt][nt][q] = 0.f;

    load_chunk(0);
    store_chunk(0);
    __syncthreads();

    const uint4* bptr = Bfrag + ((size_t)warp_n * 4 * NKS) * 32 + lane;

    #pragma unroll
    for (int c = 0; c < NCHUNK; ++c) {
        int buf = c & 1;
        if (c + 1 < NCHUNK) load_chunk((c + 1) * 64);

        const uint32_t sAhi_u = smem_u32(sAhi[buf]);
        const uint32_t sAlo_u = smem_u32(sAlo[buf]);

        #pragma unroll
        for (int ks = 0; ks < 4; ++ks) {
            int kks = c * 4 + ks;
            uint32_t ahi[2][4], alo[2][4];
            #pragma unroll
            for (int mt = 0; mt < 2; ++mt) {
                int row = warp_m * 32 + mt * 16 + (lane & 15);
                int koff = ks * 16 + (lane >> 4) * 8;
                uint32_t byteoff = (uint32_t)(row * A_STRIDE + koff) * 2;
                ldsm4(ahi[mt], sAhi_u + byteoff);
                ldsm4(alo[mt], sAlo_u + byteoff);
            }
            #pragma unroll
            for (int nt = 0; nt < 4; ++nt) {
                uint4 b = __ldg(bptr + ((size_t)nt * NKS + kks) * 32);
                #pragma unroll
                for (int mt = 0; mt < 2; ++mt) {
                    mma16816(acc[mt][nt], ahi[mt], b.x, b.y);
                    mma16816(acc[mt][nt], ahi[mt], b.z, b.w);
                    mma16816(acc[mt][nt], alo[mt], b.x, b.y);
                }
            }
        }

        if (c + 1 < NCHUNK) {
            store_chunk(1 - buf);      // buffer's last readers fenced at end of c-1
            __syncthreads();           // single barrier per chunk
        }
    }

    #pragma unroll
    for (int mt = 0; mt < 2; ++mt) {
        int r0 = rowBase + warp_m * 32 + mt * 16 + (lane >> 2);
        #pragma unroll
        for (int nt = 0; nt < 4; ++nt) {
            int col = warp_n * 32 + nt * 8 + (lane & 3) * 2;
            float v0 = acc[mt][nt][0], v1 = acc[mt][nt][1];
            float v2 = acc[mt][nt][2], v3 = acc[mt][nt][3];
            if (KIND == 1) {
                float b0 = __ldg(bias + col), b1 = __ldg(bias + col + 1);
                v0 = fmaxf(v0 + b0, 0.f); v1 = fmaxf(v1 + b1, 0.f);
                v2 = fmaxf(v2 + b0, 0.f); v3 = fmaxf(v3 + b1, 0.f);
            }
            float* dst = (KIND == 1) ? g_h : g_c2;
            if (r0 < N_NODES)
                *(float2*)(dst + (size_t)r0 * 128 + col) = make_float2(v0, v1);
            if (r0 + 8 < N_NODES)
                *(float2*)(dst + (size_t)(r0 + 8) * 128 + col) = make_float2(v2, v3);
        }
    }
}

__global__ void __launch_bounds__(256, 2) gemm1_mma(const float* __restrict__ x,
                                                    const float* __restrict__ b1) {
    gemm_mma_body<1>(x, gW1frag, b1);
}
__global__ void __launch_bounds__(256, 2) gemm2_mma() {
    gemm_mma_body<2>(nullptr, gW2frag, nullptr);
}

// ---------------------------------------------------------------------------
static inline void launch_pdl(const void* func, int grid, int block, void** args) {
    cudaLaunchConfig_t cfg = {};
    cfg.gridDim  = dim3(grid, 1, 1);
    cfg.blockDim = dim3(block, 1, 1);
    cfg.stream   = 0;
    cudaLaunchAttribute attr[1];
    attr[0].id = cudaLaunchAttributeProgrammaticStreamSerialization;
    attr[0].val.programmaticStreamSerializationAllowed = 1;
    cfg.attrs = attr;
    cfg.numAttrs = 1;
    cudaLaunchKernelExC(&cfg, func, args);
}

extern "C" void kernel_launch(void* const* d_in, const int* in_sizes, int n_in,
                              void* d_out, int out_size) {
    const float* x   = (const float*)d_in[0];
    const int*   ei  = (const int*)d_in[1];
    const float* W1l = (const float*)d_in[2];
    const float* b1  = (const float*)d_in[3];
    const float* W1r = (const float*)d_in[4];
    const float* W2l = (const float*)d_in[5];
    const float* b2  = (const float*)d_in[6];
    const float* W2r = (const float*)d_in[7];
    float* out = (float*)d_out;

    const int EB4 = (N_EDGES / 4 + 255) / 256;     // 782 (4 edges/thread)
    const int gemmBlocks = (N_NODES + 63) / 64;    // 782
    const int aggBlocks  = (N_NODES * 32 + 255) / 256;

    // head of chain: normal launch
    prep_kernel<<<NB, 256>>>(W1l, W1r, W2l, W2r);

    // dependent kernels: PDL (prologue overlaps predecessor drain; data ordered
    // by griddepcontrol.wait inside each kernel)
    {
        void* a[] = { (void*)&ei };
        launch_pdl((const void*)hist_kernel, EB4, 256, a);
    }
    {
        void* a[] = {};
        launch_pdl((const void*)scan_fused, NB, 256, a);
    }
    {
        void* a[] = { (void*)&ei };
        launch_pdl((const void*)fill_kernel, EB4, 256, a);
    }
    {
        void* a[] = { (void*)&x };
        launch_pdl((const void*)agg1_kernel, aggBlocks, 256, a);
    }
    {
        void* a[] = { (void*)&x, (void*)&b1 };
        launch_pdl((const void*)gemm1_mma, gemmBlocks, 256, a);
    }
    {
        void* a[] = {};
        launch_pdl((const void*)gemm2_mma, gemmBlocks, 256, a);
    }
    {
        void* a[] = { (void*)&out, (void*)&b2 };
        launch_pdl((const void*)agg2_kernel, aggBlocks, 256, a);
    }
}

// round 17
// speedup vs baseline: 1.1607x; 1.0227x over previous
#include <cuda_runtime.h>
#include <cuda_bf16.h>
#include <cstdint>

// ---------------------------------------------------------------------------
// SAGE 2-layer forward, GB300 (ptxas target sm_103 baseline: no tcgen05).
//   GEMMs: mma.sync m16n8k16 bf16 hi/lo split (AhBh+AhBl+AlBh), fp32 acc,
//          double-buffered staging, single __syncthreads per k-chunk.
//   CSR build: hist (rank atomics, 4 edges/thr) -> fused scan -> atomic-free fill.
//   PDL everywhere; gemm1 computes its x@W1r half BEFORE the dependency wait
//   (independent of agg1), msg1@W1l half after.
// edge_index is int32 on device.
// ---------------------------------------------------------------------------

#define N_NODES 50000
#define N_EDGES 800000
#define IN_C    128
#define HID_C   128
#define OUT_C   64
#define NB      196            // scan blocks: 196*256 = 50176 >= N_NODES

__device__ __align__(16) float g_msg1[(size_t)N_NODES * HID_C];   // mean-agg(x)
__device__ __align__(16) float g_h   [(size_t)N_NODES * HID_C];
__device__ __align__(16) float g_c2  [(size_t)N_NODES * 128];     // [t=h@W2l | hr=h@W2r]

__device__ int g_deg_i[NB * 256];
__device__ int g_off  [NB * 256];
__device__ __align__(16) int g_rank [N_EDGES];
__device__ int g_total;
__device__ int g_csr  [950016];   // padded-deg capacity: 800000 + 3*50000

// Precomputed B fragments: uint4 {bh0, bh1, bl0, bl1} per (n_tile, ks, lane).
__device__ __align__(16) uint4 gW1frag[16 * 16 * 32];
__device__ __align__(16) uint4 gW2frag[16 * 8 * 32];

// ---------------- helpers ----------------------------------------------------
__device__ __forceinline__ uint32_t smem_u32(const void* p) {
    uint32_t a;
    asm("{ .reg .u64 t; cvta.to.shared.u64 t, %1; cvt.u32.u64 %0, t; }" : "=r"(a) : "l"(p));
    return a;
}
__device__ __forceinline__ void split2(float f0, float f1, uint32_t& hi, uint32_t& lo) {
    __nv_bfloat16 h0 = __float2bfloat16(f0);
    __nv_bfloat16 h1 = __float2bfloat16(f1);
    __nv_bfloat16 l0 = __float2bfloat16(f0 - __bfloat162float(h0));
    __nv_bfloat16 l1 = __float2bfloat16(f1 - __bfloat162float(h1));
    hi = ((uint32_t)__bfloat16_as_ushort(h1) << 16) | __bfloat16_as_ushort(h0);
    lo = ((uint32_t)__bfloat16_as_ushort(l1) << 16) | __bfloat16_as_ushort(l0);
}
__device__ __forceinline__ void ldsm4(uint32_t* r, uint32_t addr) {
    asm volatile("ldmatrix.sync.aligned.m8n8.x4.shared.b16 {%0,%1,%2,%3}, [%4];"
                 : "=r"(r[0]), "=r"(r[1]), "=r"(r[2]), "=r"(r[3]) : "r"(addr));
}
__device__ __forceinline__ void mma16816(float* d, const uint32_t* a, uint32_t b0, uint32_t b1) {
    asm volatile(
        "mma.sync.aligned.m16n8k16.row.col.f32.bf16.bf16.f32 "
        "{%0,%1,%2,%3}, {%4,%5,%6,%7}, {%8,%9}, {%0,%1,%2,%3};"
        : "+f"(d[0]), "+f"(d[1]), "+f"(d[2]), "+f"(d[3])
        : "r"(a[0]), "r"(a[1]), "r"(a[2]), "r"(a[3]), "r"(b0), "r"(b1));
}
__device__ __forceinline__ void grid_dep_sync() {
    asm volatile("griddepcontrol.wait;" ::: "memory");
}
__device__ __forceinline__ void launch_deps() {
    asm volatile("griddepcontrol.launch_dependents;" ::: "memory");
}

// ---------------------------------------------------------------------------
// prep: zero degree array + global counter + build MMA-ready B fragments.
// Small grid -> launch_dependents at start so hist can prefetch ei during prep.
// ---------------------------------------------------------------------------
__global__ void prep_kernel(const float* __restrict__ W1l, const float* __restrict__ W1r,
                            const float* __restrict__ W2l, const float* __restrict__ W2r) {
    launch_deps();
    int idx = blockIdx.x * blockDim.x + threadIdx.x;
    if (idx < NB * 256) g_deg_i[idx] = 0;
    if (idx == 0) g_total = 0;

    const int total1 = 16 * 16 * 32;
    const int total2 = 16 * 8 * 32;
    if (idx < total1) {
        int lane = idx & 31, ks = (idx >> 5) & 15, ntl = idx >> 9;
        int n  = ntl * 8 + (lane >> 2);
        int k0 = ks * 16 + (lane & 3) * 2;
        float f[4];
        #pragma unroll
        for (int q = 0; q < 4; ++q) {
            int k = k0 + (q >> 1) * 8 + (q & 1);
            f[q] = (k < 128) ? __ldg(W1l + (size_t)k * 128 + n)
                             : __ldg(W1r + (size_t)(k - 128) * 128 + n);
        }
        uint4 r;
        split2(f[0], f[1], r.x, r.z);
        split2(f[2], f[3], r.y, r.w);
        gW1frag[idx] = r;
    } else if (idx < total1 + total2) {
        int j = idx - total1;
        int lane = j & 31, ks = (j >> 5) & 7, ntl = j >> 8;
        int n  = ntl * 8 + (lane >> 2);
        int k0 = ks * 16 + (lane & 3) * 2;
        float f[4];
        #pragma unroll
        for (int q = 0; q < 4; ++q) {
            int k = k0 + (q >> 1) * 8 + (q & 1);
            f[q] = (n < 64) ? __ldg(W2l + (size_t)k * 64 + n)
                            : __ldg(W2r + (size_t)k * 64 + (n - 64));
        }
        uint4 r;
        split2(f[0], f[1], r.x, r.z);
        split2(f[2], f[3], r.y, r.w);
        gW2frag[j] = r;
    }
}

// ---------------------------------------------------------------------------
// hist: rank-returning atomics, 4 edges/thr. ei loads issue before the wait.
// ---------------------------------------------------------------------------
__global__ void hist_kernel(const int* __restrict__ ei) {
    int t = blockIdx.x * blockDim.x + threadIdx.x;
    int e = t * 4;
    if (e >= N_EDGES) return;
    int4 s4 = *(const int4*)(ei + e);
    int4 d4 = *(const int4*)(ei + N_EDGES + e);
    grid_dep_sync();   // g_deg_i zeroed (prep)
    int4 r4;
    r4.x = ((unsigned)s4.x < N_NODES && (unsigned)d4.x < N_NODES) ? atomicAdd(&g_deg_i[d4.x], 1) : 0;
    r4.y = ((unsigned)s4.y < N_NODES && (unsigned)d4.y < N_NODES) ? atomicAdd(&g_deg_i[d4.y], 1) : 0;
    r4.z = ((unsigned)s4.z < N_NODES && (unsigned)d4.z < N_NODES) ? atomicAdd(&g_deg_i[d4.z], 1) : 0;
    r4.w = ((unsigned)s4.w < N_NODES && (unsigned)d4.w < N_NODES) ? atomicAdd(&g_deg_i[d4.w], 1) : 0;
    *(int4*)(g_rank + e) = r4;
}

__device__ __forceinline__ int warp_incl_scan(int v, int lane) {
    #pragma unroll
    for (int d = 1; d < 32; d <<= 1) {
        int u = __shfl_up_sync(0xFFFFFFFFu, v, d);
        if (lane >= d) v += u;
    }
    return v;
}
// Fused scan; small grid -> launch_dependents so fill prefetches ei/rank early.
__global__ void scan_fused() {
    launch_deps();
    __shared__ int wsum[8];
    __shared__ int base_s;
    int t = threadIdx.x, lane = t & 31, w = t >> 5;
    int n = blockIdx.x * 256 + t;
    grid_dep_sync();   // g_deg_i final (hist)
    int v = (n < N_NODES) ? ((g_deg_i[n] + 3) & ~3) : 0;   // pad region to 16B
    int incl = warp_incl_scan(v, lane);
    if (lane == 31) wsum[w] = incl;
    __syncthreads();
    if (w == 0) {
        int s = (lane < 8) ? wsum[lane] : 0;
        s = warp_incl_scan(s, lane);
        if (lane < 8) wsum[lane] = s;
    }
    __syncthreads();
    int wbase = (w > 0) ? wsum[w - 1] : 0;
    if (t == 255) base_s = atomicAdd(&g_total, wbase + incl);   // block sum
    __syncthreads();
    g_off[n] = base_s + wbase + incl - v;   // exclusive
}

// Atomic-free fill: slot = off[dst] + rank[e]. ei + rank loads pre-wait.
__global__ void fill_kernel(const int* __restrict__ ei) {
    int t = blockIdx.x * blockDim.x + threadIdx.x;
    int e = t * 4;
    if (e >= N_EDGES) return;
    int4 s4 = *(const int4*)(ei + e);
    int4 d4 = *(const int4*)(ei + N_EDGES + e);
    int4 r4 = *(const int4*)(g_rank + e);   // written by hist (2 back, complete)
    grid_dep_sync();   // g_off final (scan)
    if ((unsigned)s4.x < N_NODES && (unsigned)d4.x < N_NODES)
        g_csr[__ldg(g_off + d4.x) + r4.x] = s4.x;
    if ((unsigned)s4.y < N_NODES && (unsigned)d4.y < N_NODES)
        g_csr[__ldg(g_off + d4.y) + r4.y] = s4.y;
    if ((unsigned)s4.z < N_NODES && (unsigned)d4.z < N_NODES)
        g_csr[__ldg(g_off + d4.z) + r4.z] = s4.z;
    if ((unsigned)s4.w < N_NODES && (unsigned)d4.w < N_NODES)
        g_csr[__ldg(g_off + d4.w) + r4.w] = s4.w;
}

// ---------------------------------------------------------------------------
// agg1: msg1[n] = mean of x[src] over incoming edges (warp per node, d=128)
// ---------------------------------------------------------------------------
__global__ void __launch_bounds__(256) agg1_kernel(const float* __restrict__ x) {
    int w    = (blockIdx.x * blockDim.x + threadIdx.x) >> 5;
    int lane = threadIdx.x & 31;
    grid_dep_sync();   // g_csr / g_off / g_deg_i final
    if (w >= N_NODES) return;
    int deg = g_deg_i[w];
    int off = g_off[w];
    float4 acc = make_float4(0.f, 0.f, 0.f, 0.f);
    int i = 0;
    for (; i + 4 <= deg; i += 4) {
        int4 s4 = __ldg((const int4*)(g_csr + off + i));
        float4 v0 = __ldg((const float4*)(x + (size_t)s4.x * 128) + lane);
        float4 v1 = __ldg((const float4*)(x + (size_t)s4.y * 128) + lane);
        float4 v2 = __ldg((const float4*)(x + (size_t)s4.z * 128) + lane);
        float4 v3 = __ldg((const float4*)(x + (size_t)s4.w * 128) + lane);
        acc.x += v0.x + v1.x + v2.x + v3.x;
        acc.y += v0.y + v1.y + v2.y + v3.y;
        acc.z += v0.z + v1.z + v2.z + v3.z;
        acc.w += v0.w + v1.w + v2.w + v3.w;
    }
    for (; i < deg; ++i) {
        int s = __ldg(g_csr + off + i);
        float4 v = __ldg((const float4*)(x + (size_t)s * 128) + lane);
        acc.x += v.x; acc.y += v.y; acc.z += v.z; acc.w += v.w;
    }
    float rd = 1.0f / fmaxf((float)deg, 1.0f);
    acc.x *= rd; acc.y *= rd; acc.z *= rd; acc.w *= rd;
    *((float4*)(g_msg1 + (size_t)w * 128) + lane) = acc;
}

// ---------------------------------------------------------------------------
// agg2 + final epilogue: out[n] = mean(t[src]) + b2 + hr[n]   (d=64)
// ---------------------------------------------------------------------------
__global__ void __launch_bounds__(256) agg2_kernel(float* __restrict__ out,
                                                   const float* __restrict__ b2) {
    int w    = (blockIdx.x * blockDim.x + threadIdx.x) >> 5;
    int lane = threadIdx.x & 31;
    grid_dep_sync();   // g_c2 final (gemm2)
    if (w >= N_NODES) return;
    int deg = g_deg_i[w];
    int off = g_off[w];
    float2 acc = make_float2(0.f, 0.f);
    int i = 0;
    for (; i + 4 <= deg; i += 4) {
        int4 s4 = __ldg((const int4*)(g_csr + off + i));
        float2 v0 = __ldg((const float2*)(g_c2 + (size_t)s4.x * 128) + lane);
        float2 v1 = __ldg((const float2*)(g_c2 + (size_t)s4.y * 128) + lane);
        float2 v2 = __ldg((const float2*)(g_c2 + (size_t)s4.z * 128) + lane);
        float2 v3 = __ldg((const float2*)(g_c2 + (size_t)s4.w * 128) + lane);
        acc.x += v0.x + v1.x + v2.x + v3.x;
        acc.y += v0.y + v1.y + v2.y + v3.y;
    }
    for (; i < deg; ++i) {
        int s = __ldg(g_csr + off + i);
        float2 v = __ldg((const float2*)(g_c2 + (size_t)s * 128) + lane);
        acc.x += v.x; acc.y += v.y;
    }
    float rd = 1.0f / fmaxf((float)deg, 1.0f);
    float2 hr = *((const float2*)(g_c2 + (size_t)w * 128 + 64) + lane);
    float2 bb = __ldg((const float2*)b2 + lane);
    float2 o;
    o.x = acc.x * rd + bb.x + hr.x;
    o.y = acc.y * rd + bb.y + hr.y;
    *((float2*)(out + (size_t)w * 64) + lane) = o;
}

// ---------------------------------------------------------------------------
// Tensor-core GEMM: 64(M) x 128(N) CTA tile, 256 thr, 8 warps, double-buffered.
// KIND 1: chunks ordered [x0, x1, msg0, msg1]; x chunks staged+MMA'd BEFORE the
//         PDL wait (independent of agg1); wait placed before first msg1 load.
//         Epilogue bias+relu -> g_h.
// KIND 2: A = g_h (K=128), wait at start, raw store -> g_c2.
// ---------------------------------------------------------------------------
#define A_STRIDE 72   // bf16 per smem row (144B -> ldmatrix conflict-free)

template <int KIND>
__device__ __forceinline__ void gemm_mma_body(const float* __restrict__ xin,
                                              const uint4* __restrict__ Bfrag,
                                              const float* __restrict__ bias) {
    constexpr int K_TOTAL = (KIND == 1) ? 256 : 128;
    constexpr int NKS     = K_TOTAL / 16;
    constexpr int NCHUNK  = K_TOTAL / 64;

    __shared__ __nv_bfloat16 sAhi[2][64 * A_STRIDE];
    __shared__ __nv_bfloat16 sAlo[2][64 * A_STRIDE];

    const int tid    = threadIdx.x;
    const int wid    = tid >> 5;
    const int lane   = tid & 31;
    const int warp_m = wid & 1;
    const int warp_n = wid >> 1;
    const int rowBase = blockIdx.x * 64;

    if (KIND == 2) grid_dep_sync();    // KIND 1 defers the wait into the loop

    float4 pf[4];
    // KIND 1 chunk order: c=0,1 -> x cols [c*64, c*64+64); c=2,3 -> msg1
    auto load_chunk = [&](int c) {
        #pragma unroll
        for (int it = 0; it < 4; ++it) {
            int fid = tid + it * 256;
            int row = fid >> 4;
            int c4  = fid & 15;
            int gr  = rowBase + row;
            float4 v = make_float4(0.f, 0.f, 0.f, 0.f);
            if (gr < N_NODES) {
                if (KIND == 1) {
                    if (c < 2)
                        v = __ldg((const float4*)(xin + (size_t)gr * 128 + c * 64 + c4 * 4));
                    else
                        v = *(const float4*)(g_msg1 + (size_t)gr * 128 + (c - 2) * 64 + c4 * 4);
                } else {
                    v = *(const float4*)(g_h + (size_t)gr * 128 + c * 64 + c4 * 4);
                }
            }
            pf[it] = v;
        }
    };
    auto store_chunk = [&](int buf) {
        #pragma unroll
        for (int it = 0; it < 4; ++it) {
            int fid = tid + it * 256;
            int row = fid >> 4;
            int c4  = fid & 15;
            float4 v = pf[it];
            uint32_t h01, l01, h23, l23;
            split2(v.x, v.y, h01, l01);
            split2(v.z, v.w, h23, l23);
            int eoff = row * A_STRIDE + c4 * 4;
            *(uint32_t*)((char*)sAhi[buf] + eoff * 2)     = h01;
            *(uint32_t*)((char*)sAhi[buf] + eoff * 2 + 4) = h23;
            *(uint32_t*)((char*)sAlo[buf] + eoff * 2)     = l01;
            *(uint32_t*)((char*)sAlo[buf] + eoff * 2 + 4) = l23;
        }
    };

    float acc[2][4][4];
    #pragma unroll
    for (int mt = 0; mt < 2; ++mt)
        #pragma unroll
        for (int nt = 0; nt < 4; ++nt)
            #pragma unroll
            for (int q = 0; q < 4; ++q) acc[mt][nt][q] = 0.f;

    load_chunk(0);
    store_chunk(0);
    __syncthreads();

    const uint4* bptr = Bfrag + ((size_t)warp_n * 4 * NKS) * 32 + lane;

    #pragma unroll
    for (int c = 0; c < NCHUNK; ++c) {
        int buf = c & 1;
        if (c + 1 < NCHUNK) {
            if (KIND == 1 && c + 1 == 2) grid_dep_sync();   // msg1 (agg1) needed now
            load_chunk(c + 1);
        }

        const uint32_t sAhi_u = smem_u32(sAhi[buf]);
        const uint32_t sAlo_u = smem_u32(sAlo[buf]);

        // kks base: KIND1 x-chunks map to W1r (kks 8..15), msg-chunks to W1l (0..7)
        const int kksBase = (KIND == 1) ? ((c < 2) ? 8 + c * 4 : (c - 2) * 4) : c * 4;

        #pragma unroll
        for (int ks = 0; ks < 4; ++ks) {
            int kks = kksBase + ks;
            uint32_t ahi[2][4], alo[2][4];
            #pragma unroll
            for (int mt = 0; mt < 2; ++mt) {
                int row = warp_m * 32 + mt * 16 + (lane & 15);
                int koff = ks * 16 + (lane >> 4) * 8;
                uint32_t byteoff = (uint32_t)(row * A_STRIDE + koff) * 2;
                ldsm4(ahi[mt], sAhi_u + byteoff);
                ldsm4(alo[mt], sAlo_u + byteoff);
            }
            #pragma unroll
            for (int nt = 0; nt < 4; ++nt) {
                uint4 b = __ldg(bptr + ((size_t)nt * NKS + kks) * 32);
                #pragma unroll
                for (int mt = 0; mt < 2; ++mt) {
                    mma16816(acc[mt][nt], ahi[mt], b.x, b.y);
                    mma16816(acc[mt][nt], ahi[mt], b.z, b.w);
                    mma16816(acc[mt][nt], alo[mt], b.x, b.y);
                }
            }
        }

        if (c + 1 < NCHUNK) {
            store_chunk(1 - buf);      // buffer's last readers fenced at end of c-1
            __syncthreads();           // single barrier per chunk
        }
    }

    #pragma unroll
    for (int mt = 0; mt < 2; ++mt) {
        int r0 = rowBase + warp_m * 32 + mt * 16 + (lane >> 2);
        #pragma unroll
        for (int nt = 0; nt < 4; ++nt) {
            int col = warp_n * 32 + nt * 8 + (lane & 3) * 2;
            float v0 = acc[mt][nt][0], v1 = acc[mt][nt][1];
            float v2 = acc[mt][nt][2], v3 = acc[mt][nt][3];
            if (KIND == 1) {
                float b0 = __ldg(bias + col), b1 = __ldg(bias + col + 1);
                v0 = fmaxf(v0 + b0, 0.f); v1 = fmaxf(v1 + b1, 0.f);
                v2 = fmaxf(v2 + b0, 0.f); v3 = fmaxf(v3 + b1, 0.f);
            }
            float* dst = (KIND == 1) ? g_h : g_c2;
            if (r0 < N_NODES)
                *(float2*)(dst + (size_t)r0 * 128 + col) = make_float2(v0, v1);
            if (r0 + 8 < N_NODES)
                *(float2*)(dst + (size_t)(r0 + 8) * 128 + col) = make_float2(v2, v3);
        }
    }
}

__global__ void __launch_bounds__(256, 2) gemm1_mma(const float* __restrict__ x,
                                                    const float* __restrict__ b1) {
    gemm_mma_body<1>(x, gW1frag, b1);
}
__global__ void __launch_bounds__(256, 2) gemm2_mma() {
    gemm_mma_body<2>(nullptr, gW2frag, nullptr);
}

// ---------------------------------------------------------------------------
static inline void launch_pdl(const void* func, int grid, int block, void** args) {
    cudaLaunchConfig_t cfg = {};
    cfg.gridDim  = dim3(grid, 1, 1);
    cfg.blockDim = dim3(block, 1, 1);
    cfg.stream   = 0;
    cudaLaunchAttribute attr[1];
    attr[0].id = cudaLaunchAttributeProgrammaticStreamSerialization;
    attr[0].val.programmaticStreamSerializationAllowed = 1;
    cfg.attrs = attr;
    cfg.numAttrs = 1;
    cudaLaunchKernelExC(&cfg, func, args);
}

extern "C" void kernel_launch(void* const* d_in, const int* in_sizes, int n_in,
                              void* d_out, int out_size) {
    const float* x   = (const float*)d_in[0];
    const int*   ei  = (const int*)d_in[1];
    const float* W1l = (const float*)d_in[2];
    const float* b1  = (const float*)d_in[3];
    const float* W1r = (const float*)d_in[4];
    const float* W2l = (const float*)d_in[5];
    const float* b2  = (const float*)d_in[6];
    const float* W2r = (const float*)d_in[7];
    float* out = (float*)d_out;

    const int EB4 = (N_EDGES / 4 + 255) / 256;     // 782 (4 edges/thread)
    const int gemmBlocks = (N_NODES + 63) / 64;    // 782
    const int aggBlocks  = (N_NODES * 32 + 255) / 256;

    prep_kernel<<<NB, 256>>>(W1l, W1r, W2l, W2r);
    {
        void* a[] = { (void*)&ei };
        launch_pdl((const void*)hist_kernel, EB4, 256, a);
    }
    {
        void* a[] = {};
        launch_pdl((const void*)scan_fused, NB, 256, a);
    }
    {
        void* a[] = { (void*)&ei };
        launch_pdl((const void*)fill_kernel, EB4, 256, a);
    }
    {
        void* a[] = { (void*)&x };
        launch_pdl((const void*)agg1_kernel, aggBlocks, 256, a);
    }
    {
        void* a[] = { (void*)&x, (void*)&b1 };
        launch_pdl((const void*)gemm1_mma, gemmBlocks, 256, a);
    }
    {
        void* a[] = {};
        launch_pdl((const void*)gemm2_mma, gemmBlocks, 256, a);
    }
    {
        void* a[] = { (void*)&out, (void*)&b2 };
        launch_pdl((const void*)agg2_kernel, aggBlocks, 256, a);
    }
}